// round 14
// baseline (speedup 1.0000x reference)
#include <cuda_runtime.h>

// B = 16384 samples, D = 2, G = 2500 grid points.
// Y_surf: [B, 2, 2500] f32.  For each b:
//   idx = argmin_g (Ys[b,0,g]-y[b,0])^2 + (Ys[b,1,g]-y[b,1])^2
//   out[b,d] = U_grid[d, idx]
//
// R13 = interior point of the (LDG depth x warps/SM) tradeoff:
//   depth 12 (3 sequential float4 per row stream, row-grouped, guard-free)
//   __launch_bounds__(256, 3) -> 3 blocks/SM = 24 warps/SM guaranteed.
// R10 (depth 8, 29 w/SM) = 6.29 TB/s; R12 (depth 16, 16 w/SM) = 6.14.
//
// 625 = 6*96 + 49:
//   k = 0..5  : i = lane + 96k + {0,32,64}, max 575 < 625 (guard-free)
//   tail full : i = lane + 576, max 607 < 625 (guard-free)
//   tail part : i = lane + 608, valid lanes 0..16

#define G_CONST 2500
#define G4 625
#define MAIN_ITERS 6
#define WARPS_PER_BLOCK 8

__device__ __forceinline__ void upd(float d2, int g, float& best, int& bidx) {
    // strict '<' keeps FIRST minimum (per-thread indices strictly increase)
    if (d2 < best) { best = d2; bidx = g; }
}

__device__ __forceinline__ void body4(const float4& a, const float4& c,
                                      float y0, float y1, int g,
                                      float& best, int& bidx)
{
    float dx, dz;
    dx = a.x - y0; dz = c.x - y1; upd(dx*dx + dz*dz, g + 0, best, bidx);
    dx = a.y - y0; dz = c.y - y1; upd(dx*dx + dz*dz, g + 1, best, bidx);
    dx = a.z - y0; dz = c.z - y1; upd(dx*dx + dz*dz, g + 2, best, bidx);
    dx = a.w - y0; dz = c.w - y1; upd(dx*dx + dz*dz, g + 3, best, bidx);
}

__global__ __launch_bounds__(WARPS_PER_BLOCK * 32, 3)
void lqr_push_kernel13(const float* __restrict__ y,
                       const float* __restrict__ Y_surf,
                       const float* __restrict__ U_grid,
                       float* __restrict__ out,
                       int B)
{
    const int warp = threadIdx.x >> 5;
    const int lane = threadIdx.x & 31;
    const int w    = blockIdx.x * WARPS_PER_BLOCK + warp;

    const int b0 = 2 * w;
    const int b1 = 2 * w + 1;
    if (b0 >= B) return;
    const bool has1 = (b1 < B);

    const float y00 = __ldg(&y[2 * b0 + 0]);
    const float y01 = __ldg(&y[2 * b0 + 1]);
    const float y10 = has1 ? __ldg(&y[2 * b1 + 0]) : 0.0f;
    const float y11 = has1 ? __ldg(&y[2 * b1 + 1]) : 0.0f;

    const size_t row0 = (size_t)b0 * (size_t)(2 * G_CONST);
    const size_t row1 = has1 ? (size_t)b1 * (size_t)(2 * G_CONST) : row0;

    const float4* __restrict__ pa = reinterpret_cast<const float4*>(Y_surf + row0);            // s0 d0
    const float4* __restrict__ pb = reinterpret_cast<const float4*>(Y_surf + row0 + G_CONST);  // s0 d1
    const float4* __restrict__ pc = reinterpret_cast<const float4*>(Y_surf + row1);            // s1 d0
    const float4* __restrict__ pd = reinterpret_cast<const float4*>(Y_surf + row1 + G_CONST);  // s1 d1

    float best0 = 3.402823466e38f, best1 = 3.402823466e38f;
    int   idx0 = 0, idx1 = 0;

    // Main loop: 6 guard-free iterations, 12 unconditional LDG.128 each,
    // grouped by row (1.5KB sequential burst per row per body).
    #pragma unroll 1
    for (int k = 0; k < MAIN_ITERS; ++k) {
        const int i0 = lane + k * 96;
        const int i1 = i0 + 32;
        const int i2 = i0 + 64;

        const float4 a0 = __ldcs(pa + i0);
        const float4 a1 = __ldcs(pa + i1);
        const float4 a2 = __ldcs(pa + i2);
        const float4 e0 = __ldcs(pb + i0);
        const float4 e1 = __ldcs(pb + i1);
        const float4 e2 = __ldcs(pb + i2);
        const float4 c0 = __ldcs(pc + i0);
        const float4 c1 = __ldcs(pc + i1);
        const float4 c2 = __ldcs(pc + i2);
        const float4 d0 = __ldcs(pd + i0);
        const float4 d1 = __ldcs(pd + i1);
        const float4 d2 = __ldcs(pd + i2);

        body4(a0, e0, y00, y01, i0 << 2, best0, idx0);
        body4(a1, e1, y00, y01, i1 << 2, best0, idx0);
        body4(a2, e2, y00, y01, i2 << 2, best0, idx0);

        body4(c0, d0, y10, y11, i0 << 2, best1, idx1);
        body4(c1, d1, y10, y11, i1 << 2, best1, idx1);
        body4(c2, d2, y10, y11, i2 << 2, best1, idx1);
    }

    // Full tail: i = lane + 576, all lanes valid (max 607 < 625).
    {
        const int i = lane + MAIN_ITERS * 96;
        const float4 a = __ldcs(pa + i);
        const float4 e = __ldcs(pb + i);
        const float4 c = __ldcs(pc + i);
        const float4 d = __ldcs(pd + i);
        body4(a, e, y00, y01, i << 2, best0, idx0);
        body4(c, d, y10, y11, i << 2, best1, idx1);
    }

    // Partial tail: i = lane + 608, valid for lanes 0..16.
    {
        const int i = lane + MAIN_ITERS * 96 + 32;
        if (i < G4) {
            const float4 a = __ldcs(pa + i);
            const float4 e = __ldcs(pb + i);
            const float4 c = __ldcs(pc + i);
            const float4 d = __ldcs(pd + i);
            body4(a, e, y00, y01, i << 2, best0, idx0);
            body4(c, d, y10, y11, i << 2, best1, idx1);
        }
    }

    // Warp argmin reduction with first-index tie-break, both samples.
    #pragma unroll
    for (int off = 16; off > 0; off >>= 1) {
        const float ov0 = __shfl_xor_sync(0xffffffffu, best0, off);
        const int   oi0 = __shfl_xor_sync(0xffffffffu, idx0,  off);
        if (ov0 < best0 || (ov0 == best0 && oi0 < idx0)) { best0 = ov0; idx0 = oi0; }

        const float ov1 = __shfl_xor_sync(0xffffffffu, best1, off);
        const int   oi1 = __shfl_xor_sync(0xffffffffu, idx1,  off);
        if (ov1 < best1 || (ov1 == best1 && oi1 < idx1)) { best1 = ov1; idx1 = oi1; }
    }

    if (lane == 0) {
        out[2 * b0 + 0] = __ldg(&U_grid[idx0]);
        out[2 * b0 + 1] = __ldg(&U_grid[G_CONST + idx0]);
        if (has1) {
            out[2 * b1 + 0] = __ldg(&U_grid[idx1]);
            out[2 * b1 + 1] = __ldg(&U_grid[G_CONST + idx1]);
        }
    }
}

extern "C" void kernel_launch(void* const* d_in, const int* in_sizes, int n_in,
                              void* d_out, int out_size)
{
    const float* y      = (const float*)d_in[0];   // [B, 2]
    const float* Y_surf = (const float*)d_in[1];   // [B, 2, 2500]
    const float* U_grid = (const float*)d_in[2];   // [2, 2500]
    float* out = (float*)d_out;                    // [B, 2]

    const int B = in_sizes[0] / 2;

    const int threads = WARPS_PER_BLOCK * 32;                     // 256
    const int pairs   = (B + 1) / 2;                              // 2 samples/warp
    const int blocks  = (pairs + WARPS_PER_BLOCK - 1) / WARPS_PER_BLOCK;  // 1024

    lqr_push_kernel13<<<blocks, threads>>>(y, Y_surf, U_grid, out, B);
}

// round 16
// speedup vs baseline: 1.0375x; 1.0375x over previous
#include <cuda_runtime.h>

// B = 16384 samples, D = 2, G = 2500 grid points.
// Y_surf: [B, 2, 2500] f32.  For each b:
//   idx = argmin_g (Ys[b,0,g]-y[b,0])^2 + (Ys[b,1,g]-y[b,1])^2
//   out[b,d] = U_grid[d, idx]
//
// FINAL (= R10 champion): 2 interleaved samples per warp, 1024 blocks x
// 256 threads, manual unroll-2 with loads grouped by row (1KB sequential
// burst per row stream), 8 unconditional LDG.128 in flight per warp,
// __launch_bounds__(256, 1) so ptxas keeps all 32 load-destination regs
// live (regs=56 -> 4 blocks/SM = 32 warps/SM, the measured optimum of the
// depth x occupancy surface).
//
// 625 = 9*64 + 49:
//   k = 0..8 : i = lane+64k, both i and i+32 valid for ALL lanes (<= 575)
//   tail-1   : i = lane+576 valid for all lanes (<= 607)
//   tail-2   : i = lane+608 valid for lanes 0..16

#define G_CONST 2500
#define G4 625
#define MAIN_ITERS 9
#define WARPS_PER_BLOCK 8

__device__ __forceinline__ void upd(float d2, int g, float& best, int& bidx) {
    // strict '<' keeps FIRST minimum (per-thread indices strictly increase)
    if (d2 < best) { best = d2; bidx = g; }
}

__device__ __forceinline__ void body4(const float4& a, const float4& c,
                                      float y0, float y1, int g,
                                      float& best, int& bidx)
{
    float dx, dz;
    dx = a.x - y0; dz = c.x - y1; upd(dx*dx + dz*dz, g + 0, best, bidx);
    dx = a.y - y0; dz = c.y - y1; upd(dx*dx + dz*dz, g + 1, best, bidx);
    dx = a.z - y0; dz = c.z - y1; upd(dx*dx + dz*dz, g + 2, best, bidx);
    dx = a.w - y0; dz = c.w - y1; upd(dx*dx + dz*dz, g + 3, best, bidx);
}

__global__ __launch_bounds__(WARPS_PER_BLOCK * 32, 1)
void lqr_push_final(const float* __restrict__ y,
                    const float* __restrict__ Y_surf,
                    const float* __restrict__ U_grid,
                    float* __restrict__ out,
                    int B)
{
    const int warp = threadIdx.x >> 5;
    const int lane = threadIdx.x & 31;
    const int w    = blockIdx.x * WARPS_PER_BLOCK + warp;

    const int b0 = 2 * w;
    const int b1 = 2 * w + 1;
    if (b0 >= B) return;
    const bool has1 = (b1 < B);

    const float y00 = __ldg(&y[2 * b0 + 0]);
    const float y01 = __ldg(&y[2 * b0 + 1]);
    const float y10 = has1 ? __ldg(&y[2 * b1 + 0]) : 0.0f;
    const float y11 = has1 ? __ldg(&y[2 * b1 + 1]) : 0.0f;

    const size_t row0 = (size_t)b0 * (size_t)(2 * G_CONST);
    const size_t row1 = has1 ? (size_t)b1 * (size_t)(2 * G_CONST) : row0;

    const float4* __restrict__ pa = reinterpret_cast<const float4*>(Y_surf + row0);            // s0 d0
    const float4* __restrict__ pb = reinterpret_cast<const float4*>(Y_surf + row0 + G_CONST);  // s0 d1
    const float4* __restrict__ pc = reinterpret_cast<const float4*>(Y_surf + row1);            // s1 d0
    const float4* __restrict__ pd = reinterpret_cast<const float4*>(Y_surf + row1 + G_CONST);  // s1 d1

    float best0 = 3.402823466e38f, best1 = 3.402823466e38f;
    int   idx0 = 0, idx1 = 0;

    // Main loop: 9 guard-free double-iterations. Loads grouped by row so
    // each row sees a 1KB sequential burst per body; 8 LDG.128 in flight.
    #pragma unroll 1
    for (int k = 0; k < MAIN_ITERS; ++k) {
        const int i = lane + (k << 6);
        const int j = i + 32;

        const float4 a0 = __ldcs(pa + i);
        const float4 a1 = __ldcs(pa + j);
        const float4 b0v = __ldcs(pb + i);
        const float4 b1v = __ldcs(pb + j);
        const float4 c0 = __ldcs(pc + i);
        const float4 c1 = __ldcs(pc + j);
        const float4 d0 = __ldcs(pd + i);
        const float4 d1 = __ldcs(pd + j);

        body4(a0, b0v, y00, y01, i << 2, best0, idx0);
        body4(a1, b1v, y00, y01, j << 2, best0, idx0);
        body4(c0, d0,  y10, y11, i << 2, best1, idx1);
        body4(c1, d1,  y10, y11, j << 2, best1, idx1);
    }

    // Tail-1: i = lane + 576, valid for all lanes.
    {
        const int i = lane + MAIN_ITERS * 64;
        const float4 a = __ldcs(pa + i);
        const float4 bv = __ldcs(pb + i);
        const float4 c = __ldcs(pc + i);
        const float4 d = __ldcs(pd + i);
        body4(a, bv, y00, y01, i << 2, best0, idx0);
        body4(c, d,  y10, y11, i << 2, best1, idx1);
    }

    // Tail-2: i = lane + 608, valid for lanes 0..16.
    {
        const int i = lane + MAIN_ITERS * 64 + 32;
        if (i < G4) {
            const float4 a = __ldcs(pa + i);
            const float4 bv = __ldcs(pb + i);
            const float4 c = __ldcs(pc + i);
            const float4 d = __ldcs(pd + i);
            body4(a, bv, y00, y01, i << 2, best0, idx0);
            body4(c, d,  y10, y11, i << 2, best1, idx1);
        }
    }

    // Warp argmin reduction with first-index tie-break, both samples.
    #pragma unroll
    for (int off = 16; off > 0; off >>= 1) {
        const float ov0 = __shfl_xor_sync(0xffffffffu, best0, off);
        const int   oi0 = __shfl_xor_sync(0xffffffffu, idx0,  off);
        if (ov0 < best0 || (ov0 == best0 && oi0 < idx0)) { best0 = ov0; idx0 = oi0; }

        const float ov1 = __shfl_xor_sync(0xffffffffu, best1, off);
        const int   oi1 = __shfl_xor_sync(0xffffffffu, idx1,  off);
        if (ov1 < best1 || (ov1 == best1 && oi1 < idx1)) { best1 = ov1; idx1 = oi1; }
    }

    if (lane == 0) {
        out[2 * b0 + 0] = __ldg(&U_grid[idx0]);
        out[2 * b0 + 1] = __ldg(&U_grid[G_CONST + idx0]);
        if (has1) {
            out[2 * b1 + 0] = __ldg(&U_grid[idx1]);
            out[2 * b1 + 1] = __ldg(&U_grid[G_CONST + idx1]);
        }
    }
}

extern "C" void kernel_launch(void* const* d_in, const int* in_sizes, int n_in,
                              void* d_out, int out_size)
{
    const float* y      = (const float*)d_in[0];   // [B, 2]
    const float* Y_surf = (const float*)d_in[1];   // [B, 2, 2500]
    const float* U_grid = (const float*)d_in[2];   // [2, 2500]
    float* out = (float*)d_out;                    // [B, 2]

    const int B = in_sizes[0] / 2;

    const int threads = WARPS_PER_BLOCK * 32;                     // 256
    const int pairs   = (B + 1) / 2;                              // 2 samples/warp
    const int blocks  = (pairs + WARPS_PER_BLOCK - 1) / WARPS_PER_BLOCK;  // 1024

    lqr_push_final<<<blocks, threads>>>(y, Y_surf, U_grid, out, B);
}